// round 12
// baseline (speedup 1.0000x reference)
#include <cuda_runtime.h>
#include <cuda_fp16.h>
#include <cstdint>

// Problem constants
#define B_   4
#define S_   2048
#define H_   16
#define DH_  64
#define D_   1024
#define M_   (B_*S_)   // 8192 rows
#define DU   512       // row stride in uint32 (half2) units

// log2(e) folded constants
#define QSCALE 0.18033688f            // 0.125 * log2(e)
#define PEN2  -1.4426950409e10f       // -1e10 * log2(e)

// ---------------- scratch (device globals: no allocation allowed) ----------
__device__ uint32_t g_q[M_ * DU];
__device__ uint32_t g_k[M_ * DU];
__device__ uint32_t g_v[M_ * DU];
__device__ uint32_t g_ctx[M_ * DU];
__device__ uint32_t g_xh[3 * M_ * DU];       // fp16 embeddings Q,K,V
__device__ uint32_t g_wp[4 * 512 * 1024];    // packed weights [kp][n]

// ---------------- helpers ---------------------------------------------------
__device__ __forceinline__ uint32_t ph2(float a, float b) {
    __half2 h = __floats2half2_rn(a, b);
    return *reinterpret_cast<uint32_t*>(&h);
}

__device__ __forceinline__ float ex2(float x) {
    float y;
    asm("ex2.approx.f32 %0, %1;" : "=f"(y) : "f"(x));
    return y;
}

// mma.sync m16n8k16 fp16 in / fp32 accum
__device__ __forceinline__ void mma_f16(float c[4], const uint32_t a[4],
                                        uint32_t b0, uint32_t b1) {
    asm volatile(
        "mma.sync.aligned.m16n8k16.row.col.f32.f16.f16.f32 "
        "{%0,%1,%2,%3}, {%4,%5,%6,%7}, {%8,%9}, {%0,%1,%2,%3};\n"
        : "+f"(c[0]), "+f"(c[1]), "+f"(c[2]), "+f"(c[3])
        : "r"(a[0]), "r"(a[1]), "r"(a[2]), "r"(a[3]), "r"(b0), "r"(b1));
}

// ---------------- pre-pass: fp32 embeddings -> fp16 -------------------------
__global__ void conv_h(const float* __restrict__ Q, const float* __restrict__ K,
                       const float* __restrict__ V, uint32_t* __restrict__ out) {
    const float* src = (blockIdx.z == 0) ? Q : (blockIdx.z == 1) ? K : V;
    uint32_t* dst = out + (size_t)blockIdx.z * (M_ * DU);
    int id = (blockIdx.x * 256 + threadIdx.x) * 4;
    float4 a = *(const float4*)&src[2 * id];
    float4 b = *(const float4*)&src[2 * id + 4];
    *(uint4*)&dst[id] = make_uint4(ph2(a.x, a.y), ph2(a.z, a.w),
                                   ph2(b.x, b.y), ph2(b.z, b.w));
}

// ---------------- pre-pass: pack W into B k-pair layout ---------------------
__global__ void pack_w(const float* __restrict__ Wq, const float* __restrict__ Wk,
                       const float* __restrict__ Wv, const float* __restrict__ Wo,
                       uint32_t* __restrict__ out) {
    const int z = blockIdx.z;
    const float* W = (z == 0) ? Wq : (z == 1) ? Wk : (z == 2) ? Wv : Wo;
    uint32_t* dst = out + (size_t)z * (512 * 1024);
    const int kp = blockIdx.x;
    const int n4 = threadIdx.x * 4;
    float4 a = *(const float4*)&W[(2 * kp)     * 1024 + n4];
    float4 b = *(const float4*)&W[(2 * kp + 1) * 1024 + n4];
    *(uint4*)&dst[kp * 1024 + n4] =
        make_uint4(ph2(a.x, b.x), ph2(a.y, b.y), ph2(a.z, b.z), ph2(a.w, b.w));
}

// ---------------- fp16 GEMM: Y[M,1024] = X[M,1024] @ W ----------------------
#define LDA2 20
#define LDB2 136
#define ASZ2 (128 * LDA2)
#define BSZ2 (16 * LDB2)
#define NCH 32

__global__ __launch_bounds__(256, 2)
void gemm_f16(const uint32_t* __restrict__ Xb, const uint32_t* __restrict__ Wpb,
              uint32_t* __restrict__ Yh0, uint32_t* __restrict__ Yh1,
              uint32_t* __restrict__ Yh2, float* __restrict__ Yf, int mode) {
    __shared__ uint32_t As2[2 * ASZ2];
    __shared__ uint32_t Bs2[2 * BSZ2];

    const int z = blockIdx.z;
    const uint32_t* X = Xb + (size_t)z * (M_ * DU);
    const uint32_t* W = Wpb + (size_t)z * (512 * 1024);

    const int tid = threadIdx.x;
    const int lane = tid & 31;
    const int wid = tid >> 5;
    const int g = lane >> 2, t4 = lane & 3;
    const int wm = wid & 3, wn = wid >> 2;
    const int m0 = blockIdx.y * 128, n0 = blockIdx.x * 128;

    float acc[2][8][4];
#pragma unroll
    for (int am = 0; am < 2; am++)
#pragma unroll
        for (int n = 0; n < 8; n++)
#pragma unroll
            for (int e = 0; e < 4; e++) acc[am][n][e] = 0.f;

    uint4 ra[2], rb[2];

#pragma unroll
    for (int j = 0; j < 2; j++) {
        int id = tid + j * 256;
        int r = id >> 2, q4 = (id & 3) * 4;
        ra[j] = *(const uint4*)&X[(m0 + r) * DU + q4];
        int kp = id >> 5, n4 = (id & 31) * 4;
        rb[j] = *(const uint4*)&W[kp * 1024 + n0 + n4];
    }
#pragma unroll
    for (int j = 0; j < 2; j++) {
        int id = tid + j * 256;
        int r = id >> 2, q4 = (id & 3) * 4;
        *(uint4*)&As2[r * LDA2 + q4] = ra[j];
        int kp = id >> 5, n4 = (id & 31) * 4;
        *(uint4*)&Bs2[kp * LDB2 + n4] = rb[j];
    }
#pragma unroll
    for (int j = 0; j < 2; j++) {
        int id = tid + j * 256;
        int r = id >> 2, q4 = (id & 3) * 4;
        ra[j] = *(const uint4*)&X[(m0 + r) * DU + 16 + q4];
        int kp = id >> 5, n4 = (id & 31) * 4;
        rb[j] = *(const uint4*)&W[(16 + kp) * 1024 + n0 + n4];
    }
    __syncthreads();

    for (int kc = 0; kc < NCH; kc++) {
        const uint32_t* Ab = As2 + (kc & 1) * ASZ2;
        const uint32_t* Bb = Bs2 + (kc & 1) * BSZ2;

#pragma unroll
        for (int ks = 0; ks < 2; ks++) {
            const int kb = ks * 8;
            uint32_t a[2][4];
#pragma unroll
            for (int am = 0; am < 2; am++) {
                int rm = wm * 32 + am * 16;
                a[am][0] = Ab[(rm + g)     * LDA2 + kb + t4];
                a[am][1] = Ab[(rm + g + 8) * LDA2 + kb + t4];
                a[am][2] = Ab[(rm + g)     * LDA2 + kb + t4 + 4];
                a[am][3] = Ab[(rm + g + 8) * LDA2 + kb + t4 + 4];
            }
            const int cn = wn * 64;
#pragma unroll
            for (int n = 0; n < 8; n++) {
                uint32_t b0 = Bb[(kb + t4)     * LDB2 + cn + n * 8 + g];
                uint32_t b1 = Bb[(kb + t4 + 4) * LDB2 + cn + n * 8 + g];
                mma_f16(acc[0][n], a[0], b0, b1);
                mma_f16(acc[1][n], a[1], b0, b1);
            }
        }

        if (kc + 1 < NCH) {
            uint32_t* An = As2 + ((kc + 1) & 1) * ASZ2;
            uint32_t* Bn = Bs2 + ((kc + 1) & 1) * BSZ2;
#pragma unroll
            for (int j = 0; j < 2; j++) {
                int id = tid + j * 256;
                int r = id >> 2, q4 = (id & 3) * 4;
                *(uint4*)&An[r * LDA2 + q4] = ra[j];
                int kp = id >> 5, n4 = (id & 31) * 4;
                *(uint4*)&Bn[kp * LDB2 + n4] = rb[j];
            }
        }
        if (kc + 2 < NCH) {
            const int ku = (kc + 2) * 16;
#pragma unroll
            for (int j = 0; j < 2; j++) {
                int id = tid + j * 256;
                int r = id >> 2, q4 = (id & 3) * 4;
                ra[j] = *(const uint4*)&X[(m0 + r) * DU + ku + q4];
                int kp = id >> 5, n4 = (id & 31) * 4;
                rb[j] = *(const uint4*)&W[(ku + kp) * 1024 + n0 + n4];
            }
        }
        __syncthreads();
    }

    if (mode == 0) {
        uint32_t* Yh = (z == 0) ? Yh0 : (z == 1) ? Yh1 : Yh2;
        // Q output pre-scaled by 0.125*log2(e): softmax runs in exp2 domain
        const float sc = (z == 0) ? QSCALE : 1.0f;
#pragma unroll
        for (int am = 0; am < 2; am++) {
            int r0 = m0 + wm * 32 + am * 16 + g;
#pragma unroll
            for (int n = 0; n < 8; n++) {
                int cu = (n0 + wn * 64 + n * 8 + 2 * t4) >> 1;
                Yh[(r0)     * DU + cu] = ph2(acc[am][n][0] * sc, acc[am][n][1] * sc);
                Yh[(r0 + 8) * DU + cu] = ph2(acc[am][n][2] * sc, acc[am][n][3] * sc);
            }
        }
    } else {
#pragma unroll
        for (int am = 0; am < 2; am++) {
            int r0 = m0 + wm * 32 + am * 16 + g;
#pragma unroll
            for (int n = 0; n < 8; n++) {
                int c = n0 + wn * 64 + n * 8 + 2 * t4;
                *(float2*)&Yf[(r0)     * 1024 + c] =
                    make_float2(acc[am][n][0], acc[am][n][1]);
                *(float2*)&Yf[(r0 + 8) * 1024 + c] =
                    make_float2(acc[am][n][2], acc[am][n][3]);
            }
        }
    }
}

// ---------------- Flash attention (fp16 MMA, exp2-domain softmax) ----------
#define BRF 128
#define BCF 64
#define LDQ2 36
#define LDV2 72
#define FQ_OFF 0
#define FK_OFF (128 * LDQ2)
#define FP_OFF (FK_OFF + 64 * LDQ2)
#define FV_OFF (FP_OFF + 128 * LDQ2)
#define FM_OFF (FV_OFF + 32 * LDV2)
#define FSMEM_U32 (FM_OFF + 64)

__global__ __launch_bounds__(128, 3)
void flash_f16(const uint32_t* __restrict__ q, const uint32_t* __restrict__ k,
               const uint32_t* __restrict__ v, const int* __restrict__ kini,
               uint32_t* __restrict__ ctx) {
    extern __shared__ uint32_t smu[];
    uint32_t* Qs = smu + FQ_OFF;
    uint32_t* Ks = smu + FK_OFF;
    uint32_t* Ps = smu + FP_OFF;
    uint32_t* Vs = smu + FV_OFF;
    float* pmask = (float*)(smu + FM_OFF);

    const int tid = threadIdx.x;
    const int lane = tid & 31;
    const int w = tid >> 5;
    const int g = lane >> 2, t4 = lane & 3;
    const int qt = (int)gridDim.x - 1 - (int)blockIdx.x;  // heavy tiles first
    const int h = blockIdx.y, b = blockIdx.z;
    const int q0 = qt * BRF;
    const int rowbase = b * S_;
    const int hoffu = h * (DH_ / 2);

    // Q tile (already scaled by 0.125*log2e in projection)
#pragma unroll
    for (int i = 0; i < 8; i++) {
        int idx = tid + i * 128;
        int r = idx >> 3, c4 = (idx & 7) * 4;
        *(uint4*)&Qs[r * LDQ2 + c4] =
            *(const uint4*)&q[(rowbase + q0 + r) * DU + hoffu + c4];
    }

    float m_[2][2], l_[2][2];
    float o[2][8][4];
#pragma unroll
    for (int am = 0; am < 2; am++) {
        m_[am][0] = -1e30f; m_[am][1] = -1e30f;
        l_[am][0] = 0.f;    l_[am][1] = 0.f;
#pragma unroll
        for (int n = 0; n < 8; n++)
#pragma unroll
            for (int e = 0; e < 4; e++) o[am][n][e] = 0.f;
    }

    const int qb = w * 32;
    const int ktmax = 2 * qt + 1;

    for (int kt = 0; kt <= ktmax; kt++) {
        const int k0 = kt * BCF;
        __syncthreads();
#pragma unroll
        for (int i = 0; i < 4; i++) {
            int idx = tid + i * 128;
            int r = idx >> 3, c4 = (idx & 7) * 4;
            *(uint4*)&Ks[r * LDQ2 + c4] =
                *(const uint4*)&k[(rowbase + k0 + r) * DU + hoffu + c4];
        }
#pragma unroll
        for (int i = 0; i < 4; i++) {
            int u = tid + i * 128;
            int kp = u >> 4, gq4 = u & 15;
            uint2 pa = *(const uint2*)&v[(rowbase + k0 + 2 * kp)     * DU + hoffu + gq4 * 2];
            uint2 pb = *(const uint2*)&v[(rowbase + k0 + 2 * kp + 1) * DU + hoffu + gq4 * 2];
            int c4 = gq4 * 4;
            Vs[kp * LDV2 + c4 + 0] = __byte_perm(pa.x, pb.x, 0x5410);
            Vs[kp * LDV2 + c4 + 1] = __byte_perm(pa.x, pb.x, 0x7632);
            Vs[kp * LDV2 + c4 + 2] = __byte_perm(pa.y, pb.y, 0x5410);
            Vs[kp * LDV2 + c4 + 3] = __byte_perm(pa.y, pb.y, 0x7632);
        }
        if (tid < 64)
            pmask[tid] = (kini[rowbase + k0 + tid] != 0) ? 0.f : PEN2;
        __syncthreads();

        // ---- S = Q @ K^T ------------------------------------------------
        float s[2][8][4];
#pragma unroll
        for (int am = 0; am < 2; am++)
#pragma unroll
            for (int n = 0; n < 8; n++)
#pragma unroll
                for (int e = 0; e < 4; e++) s[am][n][e] = 0.f;
#pragma unroll
        for (int ks = 0; ks < 4; ks++) {
            const int kb = ks * 8;
            uint32_t a[2][4];
#pragma unroll
            for (int am = 0; am < 2; am++) {
                int rq = qb + am * 16;
                a[am][0] = Qs[(rq + g)     * LDQ2 + kb + t4];
                a[am][1] = Qs[(rq + g + 8) * LDQ2 + kb + t4];
                a[am][2] = Qs[(rq + g)     * LDQ2 + kb + t4 + 4];
                a[am][3] = Qs[(rq + g + 8) * LDQ2 + kb + t4 + 4];
            }
#pragma unroll
            for (int n = 0; n < 8; n++) {
                uint32_t b0 = Ks[(n * 8 + g) * LDQ2 + kb + t4];
                uint32_t b1 = Ks[(n * 8 + g) * LDQ2 + kb + t4 + 4];
                mma_f16(s[0][n], a[0], b0, b1);
                mma_f16(s[1][n], a[1], b0, b1);
            }
        }

        // ---- masks: causal compare only on diagonal-straddling tiles ----
        const bool diag = (k0 + BCF - 1 > q0 + qb);
#pragma unroll
        for (int am = 0; am < 2; am++) {
            const int gq0 = q0 + qb + am * 16 + g;
            const int gq1 = gq0 + 8;
            if (diag) {
#pragma unroll
                for (int n = 0; n < 8; n++) {
                    int c0 = n * 8 + 2 * t4;
#pragma unroll
                    for (int e = 0; e < 2; e++) {
                        int gk = k0 + c0 + e;
                        float pm = pmask[c0 + e];
                        s[am][n][e]     += (gk > gq0) ? PEN2 : pm;
                        s[am][n][e + 2] += (gk > gq1) ? PEN2 : pm;
                    }
                }
            } else {
#pragma unroll
                for (int n = 0; n < 8; n++) {
                    int c0 = n * 8 + 2 * t4;
#pragma unroll
                    for (int e = 0; e < 2; e++) {
                        float pm = pmask[c0 + e];
                        s[am][n][e]     += pm;
                        s[am][n][e + 2] += pm;
                    }
                }
            }

            // ---- online softmax in exp2 domain --------------------------
            float rm0 = -1e30f, rm1 = -1e30f;
#pragma unroll
            for (int n = 0; n < 8; n++) {
                rm0 = fmaxf(rm0, fmaxf(s[am][n][0], s[am][n][1]));
                rm1 = fmaxf(rm1, fmaxf(s[am][n][2], s[am][n][3]));
            }
#pragma unroll
            for (int msk = 1; msk < 4; msk <<= 1) {
                rm0 = fmaxf(rm0, __shfl_xor_sync(0xffffffffu, rm0, msk));
                rm1 = fmaxf(rm1, __shfl_xor_sync(0xffffffffu, rm1, msk));
            }
            float mn0 = fmaxf(m_[am][0], rm0), mn1 = fmaxf(m_[am][1], rm1);
            float rs0 = 0.f, rs1 = 0.f;
#pragma unroll
            for (int n = 0; n < 8; n++) {
                s[am][n][0] = ex2(s[am][n][0] - mn0);
                s[am][n][1] = ex2(s[am][n][1] - mn0);
                s[am][n][2] = ex2(s[am][n][2] - mn1);
                s[am][n][3] = ex2(s[am][n][3] - mn1);
                rs0 += s[am][n][0] + s[am][n][1];
                rs1 += s[am][n][2] + s[am][n][3];
            }
#pragma unroll
            for (int msk = 1; msk < 4; msk <<= 1) {
                rs0 += __shfl_xor_sync(0xffffffffu, rs0, msk);
                rs1 += __shfl_xor_sync(0xffffffffu, rs1, msk);
            }
            float c0s = ex2(m_[am][0] - mn0), c1s = ex2(m_[am][1] - mn1);
            l_[am][0] = l_[am][0] * c0s + rs0; m_[am][0] = mn0;
            l_[am][1] = l_[am][1] * c1s + rs1; m_[am][1] = mn1;
#pragma unroll
            for (int n = 0; n < 8; n++) {
                o[am][n][0] *= c0s; o[am][n][1] *= c0s;
                o[am][n][2] *= c1s; o[am][n][3] *= c1s;
            }

            const int rq = qb + am * 16;
#pragma unroll
            for (int n = 0; n < 8; n++) {
                Ps[(rq + g)     * LDQ2 + n * 4 + t4] = ph2(s[am][n][0], s[am][n][1]);
                Ps[(rq + g + 8) * LDQ2 + n * 4 + t4] = ph2(s[am][n][2], s[am][n][3]);
            }
        }
        __syncwarp();

        // ---- O += P @ V -------------------------------------------------
#pragma unroll
        for (int ks = 0; ks < 4; ks++) {
            const int kb = ks * 8;
            uint32_t a[2][4];
#pragma unroll
            for (int am = 0; am < 2; am++) {
                int rq = qb + am * 16;
                a[am][0] = Ps[(rq + g)     * LDQ2 + kb + t4];
                a[am][1] = Ps[(rq + g + 8) * LDQ2 + kb + t4];
                a[am][2] = Ps[(rq + g)     * LDQ2 + kb + t4 + 4];
                a[am][3] = Ps[(rq + g + 8) * LDQ2 + kb + t4 + 4];
            }
#pragma unroll
            for (int n = 0; n < 8; n++) {
                uint32_t b0 = Vs[(kb + t4)     * LDV2 + n * 8 + g];
                uint32_t b1 = Vs[(kb + t4 + 4) * LDV2 + n * 8 + g];
                mma_f16(o[0][n], a[0], b0, b1);
                mma_f16(o[1][n], a[1], b0, b1);
            }
        }
        __syncwarp();
    }

    // epilogue: normalize, store ctx (fp16)
#pragma unroll
    for (int am = 0; am < 2; am++) {
        float inv0 = 1.f / l_[am][0], inv1 = 1.f / l_[am][1];
        const int r0 = rowbase + q0 + qb + am * 16 + g;
#pragma unroll
        for (int n = 0; n < 8; n++) {
            int cu = hoffu + n * 4 + t4;
            ctx[(r0)     * DU + cu] = ph2(o[am][n][0] * inv0, o[am][n][1] * inv0);
            ctx[(r0 + 8) * DU + cu] = ph2(o[am][n][2] * inv1, o[am][n][3] * inv1);
        }
    }
}

// ---------------- launch -----------------------------------------------------
extern "C" void kernel_launch(void* const* d_in, const int* in_sizes, int n_in,
                              void* d_out, int out_size) {
    const float* Q_emb = (const float*)d_in[0];
    const float* K_emb = (const float*)d_in[1];
    const float* V_emb = (const float*)d_in[2];
    // d_in[3] = Q_ini (unused by reference math)
    const int*   K_ini = (const int*)d_in[4];
    const float* WQ = (const float*)d_in[5];
    const float* WK = (const float*)d_in[6];
    const float* WV = (const float*)d_in[7];
    const float* WO = (const float*)d_in[8];
    float* out = (float*)d_out;

    uint32_t *gq, *gk, *gv, *gctx, *gxh, *gwp;
    cudaGetSymbolAddress((void**)&gq,   g_q);
    cudaGetSymbolAddress((void**)&gk,   g_k);
    cudaGetSymbolAddress((void**)&gv,   g_v);
    cudaGetSymbolAddress((void**)&gctx, g_ctx);
    cudaGetSymbolAddress((void**)&gxh,  g_xh);
    cudaGetSymbolAddress((void**)&gwp,  g_wp);

    const int smem_flash = FSMEM_U32 * (int)sizeof(uint32_t);
    cudaFuncSetAttribute(flash_f16, cudaFuncAttributeMaxDynamicSharedMemorySize,
                         smem_flash);

    conv_h<<<dim3(M_ * DU / 1024, 1, 3), 256>>>(Q_emb, K_emb, V_emb, gxh);
    pack_w<<<dim3(512, 1, 4), 256>>>(WQ, WK, WV, WO, gwp);

    gemm_f16<<<dim3(8, 64, 3), 256>>>(gxh, gwp, gq, gk, gv, nullptr, 0);

    dim3 fgrid(S_ / BRF, H_, B_);
    flash_f16<<<fgrid, 128, smem_flash>>>(gq, gk, gv, K_ini, gctx);

    gemm_f16<<<dim3(8, 64, 1), 256>>>(gctx, gwp + (size_t)3 * 512 * 1024,
                                      nullptr, nullptr, nullptr, out, 1);
}